// round 9
// baseline (speedup 1.0000x reference)
#include <cuda_runtime.h>
#include <cstdint>
#include <cstddef>

// ---------------------------------------------------------------------------
// GAT, N=6144, F_in=256, F_hid=64, F_out=32, H=4, dense adj.
// attn_ij = w_ij / sum_j w_ij with
//   w_ij = mask_ij * ( s2_j >= -s1_i ?  e^{s2_j} * e^{0.8 s1_i}  :  e^{0.2 s2_j} )
// (the common factor e^{0.2 s1_i} cancels in the softmax ratio).
// ---------------------------------------------------------------------------

constexpr int N_  = 6144;
constexpr int NH_ = 4;
constexpr int F1_ = 64;
constexpr int F2_ = 32;
constexpr int MW_ = N_ / 32;   // 192 mask words per row

struct Scratch {
    uint32_t mask[(size_t)N_ * MW_];
    float H1[(size_t)NH_ * N_ * F1_];
    float O1[(size_t)NH_ * N_ * F1_];
    float x2[(size_t)N_ * F1_];
    float H2[(size_t)N_ * F2_];
    float T1[NH_ * N_], R1[NH_ * N_], S21[NH_ * N_], E2p1[NH_ * N_], E2n1[NH_ * N_];
    float T2[N_], R2[N_], S22[N_], E2p2[N_], E2n2[N_];
};
__device__ Scratch g_s;

// ---------------- f32x2 helpers (Blackwell packed fp32) --------------------
__device__ __forceinline__ unsigned long long pk2(float lo, float hi) {
    unsigned long long d;
    asm("mov.b64 %0, {%1, %2};" : "=l"(d)
        : "r"(__float_as_uint(lo)), "r"(__float_as_uint(hi)));
    return d;
}
__device__ __forceinline__ void upk2(unsigned long long v, float& lo, float& hi) {
    unsigned int a, b;
    asm("mov.b64 {%0, %1}, %2;" : "=r"(a), "=r"(b) : "l"(v));
    lo = __uint_as_float(a); hi = __uint_as_float(b);
}
__device__ __forceinline__ unsigned long long fma2(unsigned long long a,
                                                   unsigned long long b,
                                                   unsigned long long c) {
    unsigned long long d;
    asm("fma.rn.f32x2 %0, %1, %2, %3;" : "=l"(d) : "l"(a), "l"(b), "l"(c));
    return d;
}
__device__ __forceinline__ unsigned long long add2(unsigned long long a,
                                                   unsigned long long b) {
    unsigned long long d;
    asm("add.rn.f32x2 %0, %1, %2;" : "=l"(d) : "l"(a), "l"(b));
    return d;
}

// ---------------- adj -> bitmask -------------------------------------------
__global__ void pack_kernel(const int* __restrict__ adj, uint32_t* __restrict__ mb) {
    size_t gid = (size_t)blockIdx.x * blockDim.x + threadIdx.x;
    int v = adj[gid] > 0;
    uint32_t m = __ballot_sync(0xffffffffu, v);
    if ((threadIdx.x & 31) == 0) mb[gid >> 5] = m;
}

// ---------------- small fp32 GEMM: C[h] = A @ B[h] -------------------------
// A [N_, K], B [NH][K][F], C [NH][N_][F].
template <int F>
__global__ void gemm_kernel(const float* __restrict__ A, const float* __restrict__ B,
                            float* __restrict__ C, int K) {
    constexpr int TX = F / 4;
    constexpr int TY = 256 / TX;
    constexpr int RM = TY * 4;
    constexpr int TK = 16;
    __shared__ float xs[RM][TK + 1];
    __shared__ float ws[TK][F + 4];
    const int h  = blockIdx.y;
    const int i0 = blockIdx.x * RM;
    const float* Bh = B + (size_t)h * K * F;
    float*       Ch = C + (size_t)h * N_ * F;
    const int tid = threadIdx.x;
    const int tx = tid % TX, ty = tid / TX;
    float acc[4][4] = {};
    for (int k0 = 0; k0 < K; k0 += TK) {
        for (int idx = tid; idx < RM * TK; idx += 256) {
            int r = idx / TK, c = idx % TK;
            xs[r][c] = A[(size_t)(i0 + r) * K + k0 + c];
        }
        for (int idx = tid; idx < TK * F; idx += 256) {
            int r = idx / F, c = idx % F;
            ws[r][c] = Bh[(size_t)(k0 + r) * F + c];
        }
        __syncthreads();
#pragma unroll
        for (int kk = 0; kk < TK; kk++) {
            float a[4], b[4];
#pragma unroll
            for (int r = 0; r < 4; r++) a[r] = xs[ty * 4 + r][kk];
#pragma unroll
            for (int c = 0; c < 4; c++) b[c] = ws[kk][tx * 4 + c];
#pragma unroll
            for (int r = 0; r < 4; r++)
#pragma unroll
                for (int c = 0; c < 4; c++)
                    acc[r][c] = fmaf(a[r], b[c], acc[r][c]);
        }
        __syncthreads();
    }
#pragma unroll
    for (int r = 0; r < 4; r++)
#pragma unroll
        for (int c = 0; c < 4; c++)
            Ch[(size_t)(i0 + ty * 4 + r) * F + tx * 4 + c] = acc[r][c];
}

// ---------------- per-node scores + precomputed exponentials ---------------
template <int F>
__global__ void scores_kernel(const float* __restrict__ H, const float* __restrict__ a,
                              float* __restrict__ T, float* __restrict__ R,
                              float* __restrict__ S2, float* __restrict__ E2p,
                              float* __restrict__ E2n, int NH) {
    int gw   = (int)((blockIdx.x * blockDim.x + threadIdx.x) >> 5);
    int lane = threadIdx.x & 31;
    if (gw >= NH * N_) return;
    int h = gw / N_, i = gw % N_;
    const float* Hi = H + ((size_t)h * N_ + i) * F;
    const float* a1 = a + (size_t)h * 2 * F;
    const float* a2 = a1 + F;
    float s1 = 0.f, s2 = 0.f;
    for (int f = lane; f < F; f += 32) {
        float hv = Hi[f];
        s1 = fmaf(hv, a1[f], s1);
        s2 = fmaf(hv, a2[f], s2);
    }
#pragma unroll
    for (int o = 16; o; o >>= 1) {
        s1 += __shfl_xor_sync(0xffffffffu, s1, o);
        s2 += __shfl_xor_sync(0xffffffffu, s2, o);
    }
    if (lane == 0) {
        int idx = h * N_ + i;
        T[idx]   = -s1;
        R[idx]   = expf(0.8f * s1);
        S2[idx]  = s2;
        E2p[idx] = expf(s2);
        E2n[idx] = expf(0.2f * s2);
    }
}

// ---------------- fused masked-softmax attention ---------------------------
// Out[h][i][f] = (sum_j w_ij H[h][j][f]) / (sum_j w_ij), optional elu.
template <int F, int Mi, int THREADS>
__global__ void __launch_bounds__(THREADS, 2)
attn_kernel(const float* __restrict__ H, const float* __restrict__ T,
            const float* __restrict__ R, const float* __restrict__ S2,
            const float* __restrict__ E2p, const float* __restrict__ E2n,
            const uint32_t* __restrict__ mask, float* __restrict__ Out,
            int applyElu) {
    constexpr int Q   = F / 4;          // float4 quads per row
    constexpr int G   = THREADS / Q;    // rowpair groups
    constexpr int RP  = Mi / 2;         // rowpairs per block
    constexpr int KR  = RP / G;         // rowpairs per thread
    constexpr int SW2 = Mi + 2;         // smem row stride (even; avoids conflicts)
    constexpr int IG  = THREADS / 64;   // phase-1 i-groups
    constexpr int KI  = Mi / IG;        // phase-1 i-iters per thread

    __shared__ __align__(16) float sw[64 * SW2];
    __shared__ float sT[Mi], sR[Mi];

    const int h   = blockIdx.y;
    const int i0  = blockIdx.x * Mi;
    const int tid = threadIdx.x;

    const float* Hh  = H   + (size_t)h * N_ * F;
    const float* Th  = T   + (size_t)h * N_;
    const float* Rh  = R   + (size_t)h * N_;
    const float* S2h = S2  + (size_t)h * N_;
    const float* Pph = E2p + (size_t)h * N_;
    const float* Pnh = E2n + (size_t)h * N_;

    for (int i = tid; i < Mi; i += THREADS) { sT[i] = Th[i0 + i]; sR[i] = Rh[i0 + i]; }

    // phase-1 coords
    const int jj1  = tid & 63;
    const int ib1  = tid >> 6;
    const int bit1 = jj1 & 31;
    const int wsel = jj1 >> 5;
    // phase-2 coords
    const int lane = tid & 31;
    const int warp = tid >> 5;
    const int fq   = lane % Q;
    const int rg   = warp * (32 / Q) + lane / Q;

    unsigned long long acc[KR][4];
    unsigned long long ds[KR];
#pragma unroll
    for (int k = 0; k < KR; k++) {
        ds[k] = 0ull;
#pragma unroll
        for (int q = 0; q < 4; q++) acc[k][q] = 0ull;
    }
    __syncthreads();

    for (int j0 = 0; j0 < N_; j0 += 64) {
        // ---- phase 1: w tile into smem (transposed [jj][i]) ----
        {
            const float e2p = Pph[j0 + jj1];
            const float e2n = Pnh[j0 + jj1];
            const float s2v = S2h[j0 + jj1];
            const uint32_t* mrow = mask + (size_t)i0 * MW_ + (j0 >> 5) + wsel;
#pragma unroll
            for (int k = 0; k < KI; k++) {
                int il = ib1 + IG * k;
                uint32_t wword = mrow[(size_t)il * MW_];
                float w = 0.f;
                if ((wword >> bit1) & 1u)
                    w = (s2v >= sT[il]) ? e2p * sR[il] : e2n;
                sw[jj1 * SW2 + il] = w;
            }
        }
        __syncthreads();
        // ---- phase 2: packed-rowpair FMA over the tile ----
#pragma unroll 4
        for (int jj = 0; jj < 64; jj++) {
            const float4 hv =
                *reinterpret_cast<const float4*>(Hh + (size_t)(j0 + jj) * F + 4 * fq);
            unsigned long long hx = pk2(hv.x, hv.x);
            unsigned long long hy = pk2(hv.y, hv.y);
            unsigned long long hz = pk2(hv.z, hv.z);
            unsigned long long hw = pk2(hv.w, hv.w);
            const float* swj = sw + jj * SW2;
#pragma unroll
            for (int k = 0; k < KR; k++) {
                int rp = rg + G * k;
                unsigned long long w2 =
                    *reinterpret_cast<const unsigned long long*>(swj + 2 * rp);
                acc[k][0] = fma2(w2, hx, acc[k][0]);
                acc[k][1] = fma2(w2, hy, acc[k][1]);
                acc[k][2] = fma2(w2, hz, acc[k][2]);
                acc[k][3] = fma2(w2, hw, acc[k][3]);
                ds[k]     = add2(ds[k], w2);
            }
        }
        __syncthreads();
    }

    // ---- epilogue: divide by denominator, optional elu, store ----
#pragma unroll
    for (int k = 0; k < KR; k++) {
        float d0, d1;
        upk2(ds[k], d0, d1);
        float r0 = 1.0f / d0, r1 = 1.0f / d1;
        int rp = rg + G * k;
        int ia = i0 + 2 * rp, ib = ia + 1;
        float* oa = Out + ((size_t)h * N_ + ia) * F + 4 * fq;
        float* ob = Out + ((size_t)h * N_ + ib) * F + 4 * fq;
#pragma unroll
        for (int q = 0; q < 4; q++) {
            float a0, a1;
            upk2(acc[k][q], a0, a1);
            float v0 = a0 * r0, v1 = a1 * r1;
            if (applyElu) {
                v0 = v0 > 0.f ? v0 : expf(v0) - 1.f;
                v1 = v1 > 0.f ? v1 : expf(v1) - 1.f;
            }
            oa[q] = v0;
            ob[q] = v1;
        }
    }
}

// ---------------- head combine: x2 = mean_h elu(O1[h]) ---------------------
__global__ void combine_kernel(const float* __restrict__ O1, float* __restrict__ x2) {
    int idx = blockIdx.x * blockDim.x + threadIdx.x;
    const int n = N_ * F1_;
    if (idx >= n) return;
    float s = 0.f;
#pragma unroll
    for (int h = 0; h < NH_; h++) {
        float v = O1[(size_t)h * n + idx];
        s += (v > 0.f) ? v : (expf(v) - 1.f);
    }
    x2[idx] = 0.25f * s;
}

// ---------------------------------------------------------------------------
extern "C" void kernel_launch(void* const* d_in, const int* /*in_sizes*/, int /*n_in*/,
                              void* d_out, int /*out_size*/) {
    const float* x   = (const float*)d_in[0];
    const int*   adj = (const int*)d_in[1];
    const float* Wh  = (const float*)d_in[2];
    const float* ah  = (const float*)d_in[3];
    const float* Wo  = (const float*)d_in[4];
    const float* ao  = (const float*)d_in[5];
    float*       out = (float*)d_out;

    void* sp = nullptr;
    cudaGetSymbolAddress(&sp, g_s);
    Scratch* s = (Scratch*)sp;

    // 1) adj -> bitmask (4.7 MB, L2-resident afterwards)
    pack_kernel<<<(unsigned)((size_t)N_ * N_ / 256), 256>>>(adj, s->mask);
    // 2) layer-1 head transforms: H1[h] = x @ W_heads[h]
    gemm_kernel<F1_><<<dim3(N_ / 64, NH_), 256>>>(x, Wh, s->H1, 256);
    // 3) per-node scores & exponentials
    scores_kernel<F1_><<<(NH_ * N_) / 8, 256>>>(s->H1, ah, s->T1, s->R1, s->S21,
                                                s->E2p1, s->E2n1, NH_);
    // 4) fused masked-softmax attention, 4 heads
    attn_kernel<F1_, 128, 256><<<dim3(N_ / 128, NH_), 256>>>(
        s->H1, s->T1, s->R1, s->S21, s->E2p1, s->E2n1, s->mask, s->O1, 0);
    // 5) x2 = mean_h elu(head outputs)
    combine_kernel<<<(N_ * F1_) / 256, 256>>>(s->O1, s->x2);
    // 6) layer-2 transform: H2 = x2 @ W_out
    gemm_kernel<F2_><<<dim3(N_ / 128, 1), 256>>>(s->x2, Wo, s->H2, 64);
    // 7) layer-2 scores
    scores_kernel<F2_><<<N_ / 8, 256>>>(s->H2, ao, s->T2, s->R2, s->S22,
                                        s->E2p2, s->E2n2, 1);
    // 8) final attention + elu straight into d_out
    attn_kernel<F2_, 32, 128><<<dim3(N_ / 32, 1), 128>>>(
        s->H2, s->T2, s->R2, s->S22, s->E2p2, s->E2n2, s->mask, out, 1);
}

// round 10
// speedup vs baseline: 1.3969x; 1.3969x over previous
#include <cuda_runtime.h>
#include <cstdint>
#include <cstddef>

// ---------------------------------------------------------------------------
// GAT, N=6144, F_in=256, F_hid=64, F_out=32, H=4, dense adj.
// attn_ij = w_ij / sum_j w_ij with
//   w_ij = mask_ij * ( s2_j >= -s1_i ?  e^{s2_j} * e^{0.8 s1_i}  :  e^{0.2 s2_j} )
// (the common factor e^{0.2 s1_i} cancels in the softmax ratio).
// This round: occupancy fix (64-row tiles, 128-thr blocks, 5 CTA/SM),
// j-split partials for load balance, bank-conflict-free phase-1.
// ---------------------------------------------------------------------------

typedef unsigned long long ull;

constexpr int N_  = 6144;
constexpr int NH_ = 4;
constexpr int F1_ = 64;
constexpr int F2_ = 32;
constexpr int MW_ = N_ / 32;   // 192 mask words per row
constexpr int JS1_ = 2;        // j-splits, layer 1
constexpr int JS2_ = 4;        // j-splits, layer 2

struct Scratch {
    uint32_t mask[(size_t)N_ * MW_];
    float H1[(size_t)NH_ * N_ * F1_];
    float P1n[(size_t)JS1_ * NH_ * N_ * F1_];
    float P1d[(size_t)JS1_ * NH_ * N_];
    float x2[(size_t)N_ * F1_];
    float H2[(size_t)N_ * F2_];
    float P2n[(size_t)JS2_ * N_ * F2_];
    float P2d[(size_t)JS2_ * N_];
    float T1[NH_ * N_], R1[NH_ * N_], S21[NH_ * N_], E2p1[NH_ * N_], E2n1[NH_ * N_];
    float T2[N_], R2[N_], S22[N_], E2p2[N_], E2n2[N_];
};
__device__ Scratch g_s;

// ---------------- f32x2 helpers (Blackwell packed fp32) --------------------
__device__ __forceinline__ ull pk2(float lo, float hi) {
    ull d;
    asm("mov.b64 %0, {%1, %2};" : "=l"(d)
        : "r"(__float_as_uint(lo)), "r"(__float_as_uint(hi)));
    return d;
}
__device__ __forceinline__ void upk2(ull v, float& lo, float& hi) {
    unsigned int a, b;
    asm("mov.b64 {%0, %1}, %2;" : "=r"(a), "=r"(b) : "l"(v));
    lo = __uint_as_float(a); hi = __uint_as_float(b);
}
__device__ __forceinline__ ull fma2(ull a, ull b, ull c) {
    ull d;
    asm("fma.rn.f32x2 %0, %1, %2, %3;" : "=l"(d) : "l"(a), "l"(b), "l"(c));
    return d;
}
__device__ __forceinline__ ull add2(ull a, ull b) {
    ull d;
    asm("add.rn.f32x2 %0, %1, %2;" : "=l"(d) : "l"(a), "l"(b));
    return d;
}

// ---------------- adj -> bitmask -------------------------------------------
__global__ void pack_kernel(const int* __restrict__ adj, uint32_t* __restrict__ mb) {
    size_t gid = (size_t)blockIdx.x * blockDim.x + threadIdx.x;
    int v = adj[gid] > 0;
    uint32_t m = __ballot_sync(0xffffffffu, v);
    if ((threadIdx.x & 31) == 0) mb[gid >> 5] = m;
}

// ---------------- small fp32 GEMM: C[h] = A @ B[h] -------------------------
template <int F>
__global__ void gemm_kernel(const float* __restrict__ A, const float* __restrict__ B,
                            float* __restrict__ C, int K) {
    constexpr int TX = F / 4;
    constexpr int TY = 256 / TX;
    constexpr int RM = TY * 4;
    constexpr int TK = 16;
    __shared__ float xs[RM][TK + 1];
    __shared__ float ws[TK][F + 4];
    const int h  = blockIdx.y;
    const int i0 = blockIdx.x * RM;
    const float* Bh = B + (size_t)h * K * F;
    float*       Ch = C + (size_t)h * N_ * F;
    const int tid = threadIdx.x;
    const int tx = tid % TX, ty = tid / TX;
    float acc[4][4] = {};
    for (int k0 = 0; k0 < K; k0 += TK) {
        for (int idx = tid; idx < RM * TK; idx += 256) {
            int r = idx / TK, c = idx % TK;
            xs[r][c] = A[(size_t)(i0 + r) * K + k0 + c];
        }
        for (int idx = tid; idx < TK * F; idx += 256) {
            int r = idx / F, c = idx % F;
            ws[r][c] = Bh[(size_t)(k0 + r) * F + c];
        }
        __syncthreads();
#pragma unroll
        for (int kk = 0; kk < TK; kk++) {
            float a[4], b[4];
#pragma unroll
            for (int r = 0; r < 4; r++) a[r] = xs[ty * 4 + r][kk];
#pragma unroll
            for (int c = 0; c < 4; c++) b[c] = ws[kk][tx * 4 + c];
#pragma unroll
            for (int r = 0; r < 4; r++)
#pragma unroll
                for (int c = 0; c < 4; c++)
                    acc[r][c] = fmaf(a[r], b[c], acc[r][c]);
        }
        __syncthreads();
    }
#pragma unroll
    for (int r = 0; r < 4; r++)
#pragma unroll
        for (int c = 0; c < 4; c++)
            Ch[(size_t)(i0 + ty * 4 + r) * F + tx * 4 + c] = acc[r][c];
}

// ---------------- per-node scores + precomputed exponentials ---------------
template <int F>
__global__ void scores_kernel(const float* __restrict__ H, const float* __restrict__ a,
                              float* __restrict__ T, float* __restrict__ R,
                              float* __restrict__ S2, float* __restrict__ E2p,
                              float* __restrict__ E2n, int NH) {
    int gw   = (int)((blockIdx.x * blockDim.x + threadIdx.x) >> 5);
    int lane = threadIdx.x & 31;
    if (gw >= NH * N_) return;
    int h = gw / N_, i = gw % N_;
    const float* Hi = H + ((size_t)h * N_ + i) * F;
    const float* a1 = a + (size_t)h * 2 * F;
    const float* a2 = a1 + F;
    float s1 = 0.f, s2 = 0.f;
    for (int f = lane; f < F; f += 32) {
        float hv = Hi[f];
        s1 = fmaf(hv, a1[f], s1);
        s2 = fmaf(hv, a2[f], s2);
    }
#pragma unroll
    for (int o = 16; o; o >>= 1) {
        s1 += __shfl_xor_sync(0xffffffffu, s1, o);
        s2 += __shfl_xor_sync(0xffffffffu, s2, o);
    }
    if (lane == 0) {
        int idx = h * N_ + i;
        T[idx]   = -s1;
        R[idx]   = expf(0.8f * s1);
        S2[idx]  = s2;
        E2p[idx] = expf(s2);
        E2n[idx] = expf(0.2f * s2);
    }
}

// ---------------- fused masked-softmax attention (raw partials) ------------
// Pn[js][h][i][f] += sum_{j in split} w_ij H[h][j][f];  Pd[js][h][i] += sum w_ij.
template <int F, int THREADS>
__global__ void __launch_bounds__(THREADS, 5)
attn_kernel(const float* __restrict__ H, const float* __restrict__ T,
            const float* __restrict__ R, const float* __restrict__ S2,
            const float* __restrict__ E2p, const float* __restrict__ E2n,
            const uint32_t* __restrict__ mask,
            float* __restrict__ Pn, float* __restrict__ Pd, int jsCount) {
    constexpr int Mi  = 64;
    constexpr int Q   = F / 4;          // float4 quads per row
    constexpr int G   = THREADS / Q;    // rowpair groups
    constexpr int RP  = Mi / 2;         // rowpairs per block
    constexpr int KR  = RP / G;         // rowpairs per thread
    constexpr int SW2 = Mi + 2;         // smem row stride (8B-aligned pairs)
    static_assert(THREADS == 128, "phase-1 mapping assumes 128 threads");

    __shared__ __align__(16) float sw[64 * SW2];
    __shared__ float sT[Mi], sR[Mi];

    const int h   = blockIdx.y;
    const int NHv = gridDim.y;
    const int i0  = blockIdx.x * Mi;
    const int js  = blockIdx.z;
    const int jLen   = N_ / jsCount;
    const int jStart = js * jLen;
    const int tid = threadIdx.x;

    const float* Hh  = H   + (size_t)h * N_ * F;
    const float* Th  = T   + (size_t)h * N_;
    const float* Rh  = R   + (size_t)h * N_;
    const float* S2h = S2  + (size_t)h * N_;
    const float* Pph = E2p + (size_t)h * N_;
    const float* Pnh = E2n + (size_t)h * N_;

    for (int i = tid; i < Mi; i += THREADS) { sT[i] = Th[i0 + i]; sR[i] = Rh[i0 + i]; }

    // phase-1 coords: lane varies over jj -> broadcast mask word, 2-way STS max
    const int jj1   = tid & 63;
    const int ibase = (tid >> 6) * 32;
    const int bitp  = jj1 & 31;
    // phase-2 coords
    const int lane = tid & 31;
    const int warp = tid >> 5;
    const int fq   = lane % Q;
    const int rg   = warp * (32 / Q) + lane / Q;

    ull acc[KR][4];
    ull ds[KR];
#pragma unroll
    for (int k = 0; k < KR; k++) {
        ds[k] = 0ull;
#pragma unroll
        for (int q = 0; q < 4; q++) acc[k][q] = 0ull;
    }
    __syncthreads();

    for (int j0 = 0; j0 < jLen; j0 += 64) {
        const int jA = jStart + j0;
        // ---- phase 1: w tile into smem (transposed [jj][i]) ----
        {
            const float e2p = Pph[jA + jj1];
            const float e2n = Pnh[jA + jj1];
            const float s2v = S2h[jA + jj1];
            const uint32_t* mw = mask + (size_t)(i0 + ibase) * MW_ + (jA >> 5) + (jj1 >> 5);
            float* swc = sw + jj1 * SW2 + ibase;
#pragma unroll 8
            for (int c = 0; c < 32; c++) {
                uint32_t wd = mw[(size_t)c * MW_];   // broadcast within warp
                int il = ibase + c;
                float w = 0.f;
                if ((wd >> bitp) & 1u)
                    w = (s2v >= sT[il]) ? e2p * sR[il] : e2n;
                swc[c] = w;
            }
        }
        __syncthreads();
        // ---- phase 2: packed-rowpair FMA over the tile ----
#pragma unroll 4
        for (int jj = 0; jj < 64; jj++) {
            const float4 hv =
                *reinterpret_cast<const float4*>(Hh + (size_t)(jA + jj) * F + 4 * fq);
            ull hx = pk2(hv.x, hv.x);
            ull hy = pk2(hv.y, hv.y);
            ull hz = pk2(hv.z, hv.z);
            ull hw = pk2(hv.w, hv.w);
            const float* swj = sw + jj * SW2 + 2 * KR * rg;  // contiguous rowpairs
#pragma unroll
            for (int k = 0; k < KR; k++) {
                ull w2 = *reinterpret_cast<const ull*>(swj + 2 * k);
                acc[k][0] = fma2(w2, hx, acc[k][0]);
                acc[k][1] = fma2(w2, hy, acc[k][1]);
                acc[k][2] = fma2(w2, hz, acc[k][2]);
                acc[k][3] = fma2(w2, hw, acc[k][3]);
                ds[k]     = add2(ds[k], w2);
            }
        }
        __syncthreads();
    }

    // ---- epilogue: store raw numerator + denominator partials ----
    const size_t base = ((size_t)(js * NHv + h)) * N_;
#pragma unroll
    for (int k = 0; k < KR; k++) {
        int rp = rg * KR + k;
        int ia = i0 + 2 * rp;
        float4 va, vb;
        upk2(acc[k][0], va.x, vb.x);
        upk2(acc[k][1], va.y, vb.y);
        upk2(acc[k][2], va.z, vb.z);
        upk2(acc[k][3], va.w, vb.w);
        *reinterpret_cast<float4*>(Pn + (base + ia) * F + 4 * fq)     = va;
        *reinterpret_cast<float4*>(Pn + (base + ia + 1) * F + 4 * fq) = vb;
        if (fq == 0) {
            float d0, d1;
            upk2(ds[k], d0, d1);
            Pd[base + ia]     = d0;
            Pd[base + ia + 1] = d1;
        }
    }
}

// ---------------- layer-1 combine: x2 = mean_h elu(sum_js Pn / sum_js Pd) --
__global__ void combine1_kernel(const float* __restrict__ Pn,
                                const float* __restrict__ Pd,
                                float* __restrict__ x2) {
    int idx = blockIdx.x * blockDim.x + threadIdx.x;
    int i = idx >> 6, f = idx & 63;
    float s = 0.f;
#pragma unroll
    for (int h = 0; h < NH_; h++) {
        float num = 0.f, den = 0.f;
#pragma unroll
        for (int js = 0; js < JS1_; js++) {
            size_t b = ((size_t)(js * NH_ + h)) * N_ + i;
            num += Pn[b * F1_ + f];
            den += Pd[b];
        }
        float v = num / den;
        s += (v > 0.f) ? v : (expf(v) - 1.f);
    }
    x2[idx] = 0.25f * s;
}

// ---------------- layer-2 finalize: out = elu(sum_js Pn / sum_js Pd) -------
__global__ void finalize2_kernel(const float* __restrict__ Pn,
                                 const float* __restrict__ Pd,
                                 float* __restrict__ out) {
    int idx = blockIdx.x * blockDim.x + threadIdx.x;
    int i = idx >> 5, f = idx & 31;
    float num = 0.f, den = 0.f;
#pragma unroll
    for (int js = 0; js < JS2_; js++) {
        size_t b = (size_t)js * N_ + i;
        num += Pn[b * F2_ + f];
        den += Pd[b];
    }
    float v = num / den;
    out[idx] = (v > 0.f) ? v : (expf(v) - 1.f);
}

// ---------------------------------------------------------------------------
extern "C" void kernel_launch(void* const* d_in, const int* /*in_sizes*/, int /*n_in*/,
                              void* d_out, int /*out_size*/) {
    const float* x   = (const float*)d_in[0];
    const int*   adj = (const int*)d_in[1];
    const float* Wh  = (const float*)d_in[2];
    const float* ah  = (const float*)d_in[3];
    const float* Wo  = (const float*)d_in[4];
    const float* ao  = (const float*)d_in[5];
    float*       out = (float*)d_out;

    void* sp = nullptr;
    cudaGetSymbolAddress(&sp, g_s);
    Scratch* s = (Scratch*)sp;

    // 1) adj -> bitmask (4.7 MB, L2-resident afterwards)
    pack_kernel<<<(unsigned)((size_t)N_ * N_ / 256), 256>>>(adj, s->mask);
    // 2) layer-1 head transforms: H1[h] = x @ W_heads[h]
    gemm_kernel<F1_><<<dim3(N_ / 64, NH_), 256>>>(x, Wh, s->H1, 256);
    // 3) per-node scores & exponentials
    scores_kernel<F1_><<<(NH_ * N_) / 8, 256>>>(s->H1, ah, s->T1, s->R1, s->S21,
                                                s->E2p1, s->E2n1, NH_);
    // 4) fused masked attention, 4 heads, 2-way j-split -> raw partials
    attn_kernel<F1_, 128><<<dim3(N_ / 64, NH_, JS1_), 128>>>(
        s->H1, s->T1, s->R1, s->S21, s->E2p1, s->E2n1, s->mask, s->P1n, s->P1d, JS1_);
    // 5) x2 = mean_h elu(num/den)
    combine1_kernel<<<(N_ * F1_) / 256, 256>>>(s->P1n, s->P1d, s->x2);
    // 6) layer-2 transform: H2 = x2 @ W_out
    gemm_kernel<F2_><<<dim3(N_ / 128, 1), 256>>>(s->x2, Wo, s->H2, 64);
    // 7) layer-2 scores
    scores_kernel<F2_><<<N_ / 8, 256>>>(s->H2, ao, s->T2, s->R2, s->S22,
                                        s->E2p2, s->E2n2, 1);
    // 8) layer-2 attention, 4-way j-split -> raw partials
    attn_kernel<F2_, 128><<<dim3(N_ / 64, 1, JS2_), 128>>>(
        s->H2, s->T2, s->R2, s->S22, s->E2p2, s->E2n2, s->mask, s->P2n, s->P2d, JS2_);
    // 9) final divide + elu straight into d_out
    finalize2_kernel<<<(N_ * F2_) / 256, 256>>>(s->P2n, s->P2d, out);
}

// round 13
// speedup vs baseline: 4.1663x; 2.9826x over previous
#include <cuda_runtime.h>
#include <cstdint>
#include <cstddef>

// ---------------------------------------------------------------------------
// GAT, N=6144, F_in=256, F_hid=64, F_out=32, H=4, dense adj.
// attn_ij = w_ij / sum_j w_ij with
//   w_ij = mask_ij * ( s2_j >= -s1_i ?  e^{s2_j} * e^{0.8 s1_i}  :  e^{0.2 s2_j} )
// This round: masked attention via legacy warp-level tf32 HMMA
// (mma.sync.m16n8k8 — base sm_80 feature, works on the sm_103 ptxas target;
// tcgen05 is 'a'-suffix-only and unavailable in this build).
// W fragments generated directly in registers (never hit smem); B = H tile
// staged in smem with cvt.rna.tf32; fp32 accumulators; exact fp32 denominator.
// ---------------------------------------------------------------------------

typedef uint32_t u32;

constexpr int N_  = 6144;
constexpr int NH_ = 4;
constexpr int F1_ = 64;
constexpr int F2_ = 32;
constexpr int MW_ = N_ / 32;   // 192 mask words per row
constexpr int JS1_ = 3;        // j-splits, layer 1 -> 576 CTAs
constexpr int JS2_ = 12;       // j-splits, layer 2 -> 576 CTAs

struct Scratch {
    u32 mask[(size_t)N_ * MW_];
    float H1[(size_t)NH_ * N_ * F1_];
    float P1n[(size_t)JS1_ * NH_ * N_ * F1_];
    float P1d[(size_t)JS1_ * NH_ * N_];
    float x2[(size_t)N_ * F1_];
    float H2[(size_t)N_ * F2_];
    float P2n[(size_t)JS2_ * N_ * F2_];
    float P2d[(size_t)JS2_ * N_];
    float T1[NH_ * N_], R1[NH_ * N_], S21[NH_ * N_], E2p1[NH_ * N_], E2n1[NH_ * N_];
    float T2[N_], R2[N_], S22[N_], E2p2[N_], E2n2[N_];
};
__device__ Scratch g_s;

// ---------------- helpers ---------------------------------------------------
__device__ __forceinline__ u32 f2tf32(float x) {
    u32 r;
    asm("cvt.rna.tf32.f32 %0, %1;" : "=r"(r) : "f"(x));
    return r;
}
__device__ __forceinline__ void mma_tf32(float& c0, float& c1, float& c2, float& c3,
                                         u32 a0, u32 a1, u32 a2, u32 a3,
                                         u32 b0, u32 b1) {
    asm volatile(
        "mma.sync.aligned.m16n8k8.row.col.f32.tf32.tf32.f32 "
        "{%0,%1,%2,%3}, {%4,%5,%6,%7}, {%8,%9}, {%0,%1,%2,%3};"
        : "+f"(c0), "+f"(c1), "+f"(c2), "+f"(c3)
        : "r"(a0), "r"(a1), "r"(a2), "r"(a3), "r"(b0), "r"(b1));
}

// ---------------- adj -> bitmask -------------------------------------------
__global__ void pack_kernel(const int* __restrict__ adj, u32* __restrict__ mb) {
    size_t gid = (size_t)blockIdx.x * blockDim.x + threadIdx.x;
    int v = adj[gid] > 0;
    u32 m = __ballot_sync(0xffffffffu, v);
    if ((threadIdx.x & 31) == 0) mb[gid >> 5] = m;
}

// ---------------- small fp32 GEMM: C[h] = A @ B[h] -------------------------
template <int F>
__global__ void gemm_kernel(const float* __restrict__ A, const float* __restrict__ B,
                            float* __restrict__ C, int K) {
    constexpr int TX = F / 4;
    constexpr int TY = 256 / TX;
    constexpr int RM = TY * 4;
    constexpr int TK = 16;
    __shared__ float xs[RM][TK + 1];
    __shared__ float ws[TK][F + 4];
    const int h  = blockIdx.y;
    const int i0 = blockIdx.x * RM;
    const float* Bh = B + (size_t)h * K * F;
    float*       Ch = C + (size_t)h * N_ * F;
    const int tid = threadIdx.x;
    const int tx = tid % TX, ty = tid / TX;
    float acc[4][4] = {};
    for (int k0 = 0; k0 < K; k0 += TK) {
        for (int idx = tid; idx < RM * TK; idx += 256) {
            int r = idx / TK, c = idx % TK;
            xs[r][c] = A[(size_t)(i0 + r) * K + k0 + c];
        }
        for (int idx = tid; idx < TK * F; idx += 256) {
            int r = idx / F, c = idx % F;
            ws[r][c] = Bh[(size_t)(k0 + r) * F + c];
        }
        __syncthreads();
#pragma unroll
        for (int kk = 0; kk < TK; kk++) {
            float a[4], b[4];
#pragma unroll
            for (int r = 0; r < 4; r++) a[r] = xs[ty * 4 + r][kk];
#pragma unroll
            for (int c = 0; c < 4; c++) b[c] = ws[kk][tx * 4 + c];
#pragma unroll
            for (int r = 0; r < 4; r++)
#pragma unroll
                for (int c = 0; c < 4; c++)
                    acc[r][c] = fmaf(a[r], b[c], acc[r][c]);
        }
        __syncthreads();
    }
#pragma unroll
    for (int r = 0; r < 4; r++)
#pragma unroll
        for (int c = 0; c < 4; c++)
            Ch[(size_t)(i0 + ty * 4 + r) * F + tx * 4 + c] = acc[r][c];
}

// ---------------- per-node scores + precomputed exponentials ---------------
template <int F>
__global__ void scores_kernel(const float* __restrict__ H, const float* __restrict__ a,
                              float* __restrict__ T, float* __restrict__ R,
                              float* __restrict__ S2, float* __restrict__ E2p,
                              float* __restrict__ E2n, int NH) {
    int gw   = (int)((blockIdx.x * blockDim.x + threadIdx.x) >> 5);
    int lane = threadIdx.x & 31;
    if (gw >= NH * N_) return;
    int h = gw / N_, i = gw % N_;
    const float* Hi = H + ((size_t)h * N_ + i) * F;
    const float* a1 = a + (size_t)h * 2 * F;
    const float* a2 = a1 + F;
    float s1 = 0.f, s2 = 0.f;
    for (int f = lane; f < F; f += 32) {
        float hv = Hi[f];
        s1 = fmaf(hv, a1[f], s1);
        s2 = fmaf(hv, a2[f], s2);
    }
#pragma unroll
    for (int o = 16; o; o >>= 1) {
        s1 += __shfl_xor_sync(0xffffffffu, s1, o);
        s2 += __shfl_xor_sync(0xffffffffu, s2, o);
    }
    if (lane == 0) {
        int idx = h * N_ + i;
        T[idx]   = -s1;
        R[idx]   = expf(0.8f * s1);
        S2[idx]  = s2;
        E2p[idx] = expf(s2);
        E2n[idx] = expf(0.2f * s2);
    }
}

// ================== tf32 HMMA masked attention =============================
// Per CTA: 128 i-rows x full F, sweeping a j-range in 32-wide tiles.
// A fragments (the attention weights w) are generated in registers; B = H
// tile staged in smem as tf32. Raw numerator/denominator partials out.
template <int F>
__global__ void __launch_bounds__(256, 2)
attn_hmma_kernel(const float* __restrict__ H, const float* __restrict__ T,
                 const float* __restrict__ R, const float* __restrict__ S2,
                 const float* __restrict__ E2p, const float* __restrict__ E2n,
                 const u32* __restrict__ mask,
                 float* __restrict__ Pn, float* __restrict__ Pd, int jsCount) {
    constexpr int SB = F + 8;          // Bs row stride (banks: 8*tg+grp distinct)
    constexpr int NT = F / 8;          // n-tiles per warp
    constexpr int QT = (32 * F / 4) / 256;  // staging float4s per thread

    __shared__ u32  Bs[2][32 * SB];
    __shared__ float sSc[2][96];       // [s2 | e2p | e2n] x 32

    const int tid  = threadIdx.x;
    const int warp = tid >> 5;
    const int lane = tid & 31;
    const int grp  = lane >> 2;
    const int tg   = lane & 3;

    const int h   = blockIdx.y;
    const int js  = blockIdx.z;
    const int i0  = blockIdx.x * 128;
    const int jLen  = N_ / jsCount;
    const int jBase = js * jLen;
    const int nTiles = jLen / 32;

    const float* Hh  = H   + (size_t)h * N_ * F;
    const float* Th  = T   + (size_t)h * N_;
    const float* Rh  = R   + (size_t)h * N_;
    const float* S2h = S2  + (size_t)h * N_;
    const float* Pph = E2p + (size_t)h * N_;
    const float* Pnh = E2n + (size_t)h * N_;

    const int rowA = i0 + warp * 16 + grp;      // global i of c0/c1
    const int rowB = rowA + 8;                  // global i of c2/c3
    const float T0 = Th[rowA], R0 = Rh[rowA];
    const float T1 = Th[rowB], R1 = Rh[rowB];

    float acc[NT][4];
#pragma unroll
    for (int nt = 0; nt < NT; nt++)
#pragma unroll
        for (int q = 0; q < 4; q++) acc[nt][q] = 0.f;
    float ds0 = 0.f, ds1 = 0.f;

    for (int t = 0; t < nTiles; t++) {
        const int buf = t & 1;
        const int jA  = jBase + t * 32;

        // mask words for this warp's two rows (issued pre-sync; L2 latency
        // hides under the staging barrier)
        const u32 mw0 = __ldg(mask + (size_t)rowA * MW_ + (jA >> 5));
        const u32 mw1 = __ldg(mask + (size_t)rowB * MW_ + (jA >> 5));

        // ---- stage B tile: Bs[j][f] = tf32(H[jA+j][f]) ----
#pragma unroll
        for (int q = 0; q < QT; q++) {
            int quad = tid + q * 256;
            int j  = quad / (F / 4);
            int fq = quad % (F / 4);
            float4 hv = *reinterpret_cast<const float4*>(Hh + (size_t)(jA + j) * F + 4 * fq);
            uint4 tv;
            tv.x = f2tf32(hv.x); tv.y = f2tf32(hv.y);
            tv.z = f2tf32(hv.z); tv.w = f2tf32(hv.w);
            *reinterpret_cast<uint4*>(&Bs[buf][j * SB + 4 * fq]) = tv;
        }
        // ---- stage score arrays ----
        if (tid < 96) {
            const float* src = (tid < 32) ? S2h : (tid < 64) ? Pph : Pnh;
            sSc[buf][tid] = src[jA + (tid & 31)];
        }
        __syncthreads();

        const float* s2p = sSc[buf];
        const float* ppp = sSc[buf] + 32;
        const float* npp = sSc[buf] + 64;

#pragma unroll
        for (int kk = 0; kk < 4; kk++) {
            const int c0 = kk * 8 + tg;
            const int c1 = c0 + 4;
            const float s2a = s2p[c0], s2b = s2p[c1];
            const float pa  = ppp[c0], pb  = ppp[c1];
            const float na  = npp[c0], nb  = npp[c1];
            float a0 = ((mw0 >> c0) & 1u) ? ((s2a >= T0) ? pa * R0 : na) : 0.f;
            float a1 = ((mw1 >> c0) & 1u) ? ((s2a >= T1) ? pa * R1 : na) : 0.f;
            float a2 = ((mw0 >> c1) & 1u) ? ((s2b >= T0) ? pb * R0 : nb) : 0.f;
            float a3 = ((mw1 >> c1) & 1u) ? ((s2b >= T1) ? pb * R1 : nb) : 0.f;
            ds0 += a0 + a2;
            ds1 += a1 + a3;
            const u32 ta0 = f2tf32(a0), ta1 = f2tf32(a1);
            const u32 ta2 = f2tf32(a2), ta3 = f2tf32(a3);
            const u32* b0p = &Bs[buf][c0 * SB + grp];
            const u32* b1p = &Bs[buf][c1 * SB + grp];
#pragma unroll
            for (int nt = 0; nt < NT; nt++)
                mma_tf32(acc[nt][0], acc[nt][1], acc[nt][2], acc[nt][3],
                         ta0, ta1, ta2, ta3, b0p[nt * 8], b1p[nt * 8]);
        }
    }

    // ---- denominator reduce across the 4 lanes of each row group ----
    ds0 += __shfl_xor_sync(0xffffffffu, ds0, 1);
    ds0 += __shfl_xor_sync(0xffffffffu, ds0, 2);
    ds1 += __shfl_xor_sync(0xffffffffu, ds1, 1);
    ds1 += __shfl_xor_sync(0xffffffffu, ds1, 2);

    // ---- store raw partials ----
    const size_t bidx = (size_t)(js * gridDim.y + h) * N_;
    float* dA = Pn + (bidx + rowA) * F;
    float* dB = Pn + (bidx + rowB) * F;
#pragma unroll
    for (int nt = 0; nt < NT; nt++) {
        float2 va = make_float2(acc[nt][0], acc[nt][1]);
        float2 vb = make_float2(acc[nt][2], acc[nt][3]);
        *reinterpret_cast<float2*>(dA + nt * 8 + 2 * tg) = va;
        *reinterpret_cast<float2*>(dB + nt * 8 + 2 * tg) = vb;
    }
    if (tg == 0) {
        Pd[bidx + rowA] = ds0;
        Pd[bidx + rowB] = ds1;
    }
}

// ---------------- layer-1 combine: x2 = mean_h elu(sum Pn / sum Pd) --------
__global__ void combine1_kernel(const float* __restrict__ Pn,
                                const float* __restrict__ Pd,
                                float* __restrict__ x2) {
    int idx = blockIdx.x * blockDim.x + threadIdx.x;
    int i = idx >> 6, f = idx & 63;
    float s = 0.f;
#pragma unroll
    for (int h = 0; h < NH_; h++) {
        float num = 0.f, den = 0.f;
#pragma unroll
        for (int js = 0; js < JS1_; js++) {
            size_t b = ((size_t)(js * NH_ + h)) * N_ + i;
            num += Pn[b * F1_ + f];
            den += Pd[b];
        }
        float v = num / den;
        s += (v > 0.f) ? v : (expf(v) - 1.f);
    }
    x2[idx] = 0.25f * s;
}

// ---------------- layer-2 finalize: out = elu(sum Pn / sum Pd) -------------
__global__ void finalize2_kernel(const float* __restrict__ Pn,
                                 const float* __restrict__ Pd,
                                 float* __restrict__ out) {
    int idx = blockIdx.x * blockDim.x + threadIdx.x;
    int i = idx >> 5, f = idx & 31;
    float num = 0.f, den = 0.f;
#pragma unroll
    for (int js = 0; js < JS2_; js++) {
        size_t b = (size_t)js * N_ + i;
        num += Pn[b * F2_ + f];
        den += Pd[b];
    }
    float v = num / den;
    out[idx] = (v > 0.f) ? v : (expf(v) - 1.f);
}

// ---------------------------------------------------------------------------
extern "C" void kernel_launch(void* const* d_in, const int* /*in_sizes*/, int /*n_in*/,
                              void* d_out, int /*out_size*/) {
    const float* x   = (const float*)d_in[0];
    const int*   adj = (const int*)d_in[1];
    const float* Wh  = (const float*)d_in[2];
    const float* ah  = (const float*)d_in[3];
    const float* Wo  = (const float*)d_in[4];
    const float* ao  = (const float*)d_in[5];
    float*       out = (float*)d_out;

    void* sp = nullptr;
    cudaGetSymbolAddress(&sp, g_s);
    Scratch* s = (Scratch*)sp;

    // 1) adj -> bitmask (4.7 MB, L2-resident afterwards)
    pack_kernel<<<(unsigned)((size_t)N_ * N_ / 256), 256>>>(adj, s->mask);
    // 2) layer-1 head transforms: H1[h] = x @ W_heads[h]
    gemm_kernel<F1_><<<dim3(N_ / 64, NH_), 256>>>(x, Wh, s->H1, 256);
    // 3) per-node scores & exponentials
    scores_kernel<F1_><<<(NH_ * N_) / 8, 256>>>(s->H1, ah, s->T1, s->R1, s->S21,
                                                s->E2p1, s->E2n1, NH_);
    // 4) tf32 HMMA masked attention, 4 heads, 3-way j-split -> raw partials
    attn_hmma_kernel<F1_><<<dim3(N_ / 128, NH_, JS1_), 256>>>(
        s->H1, s->T1, s->R1, s->S21, s->E2p1, s->E2n1, s->mask, s->P1n, s->P1d, JS1_);
    // 5) x2 = mean_h elu(num/den)
    combine1_kernel<<<(N_ * F1_) / 256, 256>>>(s->P1n, s->P1d, s->x2);
    // 6) layer-2 transform: H2 = x2 @ W_out
    gemm_kernel<F2_><<<dim3(N_ / 128, 1), 256>>>(s->x2, Wo, s->H2, 64);
    // 7) layer-2 scores
    scores_kernel<F2_><<<N_ / 8, 256>>>(s->H2, ao, s->T2, s->R2, s->S22,
                                        s->E2p2, s->E2n2, 1);
    // 8) layer-2 attention, 12-way j-split -> raw partials
    attn_hmma_kernel<F2_><<<dim3(N_ / 128, 1, JS2_), 256>>>(
        s->H2, s->T2, s->R2, s->S22, s->E2p2, s->E2n2, s->mask, s->P2n, s->P2d, JS2_);
    // 9) final divide + elu straight into d_out
    finalize2_kernel<<<(N_ * F2_) / 256, 256>>>(s->P2n, s->P2d, out);
}